// round 2
// baseline (speedup 1.0000x reference)
#include <cuda_runtime.h>
#include <cuda_bf16.h>

// RobustSum L1 (IRLS, K=3) — x:(128,1024), weight:(1024,1024) fp32 -> z:(128,1024) fp32
//
// Thread-local IRLS per (b,o): c = z/D1; iterate r_i = 1/(|x_i*W_io - c|+eps),
// c = (Σ r_i·xw_i)/max(Σ r_i, 1e-12); out = D1*c.  (w>0 so Σ|w| == Σw.)
//
// R2 layout: block = 128 threads = 4 warps. Warp = 1 b-row; lane = (ihalf, o-pair):
//   ihalf = lane>>4 picks i in [0,512) or [512,1024); opair = lane&15 picks 2 o's.
// Each thread accumulates over 512 i's with PACKED f32x2 math (FFMA2/FADD2 pipes),
// partner halves combine via shfl.xor(16). |d| is a 64-bit AND -> alu pipe.
// MUFU.RCP is the predicted floor (~170k cyc chip-wide).

#define DIN     1024
#define DOUT    1024
#define KITER   3
#define EPSILON 0.001f
#define TBROWS  4
#define NTHREADS 128

typedef unsigned long long ull;

__device__ __forceinline__ ull pack2(float lo, float hi) {
    ull r; asm("mov.b64 %0, {%1,%2};" : "=l"(r) : "f"(lo), "f"(hi)); return r;
}
__device__ __forceinline__ void unpack2(ull v, float& lo, float& hi) {
    asm("mov.b64 {%0,%1}, %2;" : "=f"(lo), "=f"(hi) : "l"(v));
}
__device__ __forceinline__ ull mul2(ull a, ull b) {
    ull r; asm("mul.rn.f32x2 %0, %1, %2;" : "=l"(r) : "l"(a), "l"(b)); return r;
}
__device__ __forceinline__ ull add2(ull a, ull b) {
    ull r; asm("add.rn.f32x2 %0, %1, %2;" : "=l"(r) : "l"(a), "l"(b)); return r;
}
__device__ __forceinline__ ull fma2(ull a, ull b, ull c) {
    ull r; asm("fma.rn.f32x2 %0, %1, %2, %3;" : "=l"(r) : "l"(a), "l"(b), "l"(c)); return r;
}
__device__ __forceinline__ float rcpf(float a) {
    float r; asm("rcp.approx.f32 %0, %1;" : "=f"(r) : "f"(a)); return r;
}

__global__ __launch_bounds__(NTHREADS, 8)
void robust_sum_kernel(const float* __restrict__ x,
                       const float* __restrict__ w,
                       float* __restrict__ out)
{
    __shared__ float xs[TBROWS][DIN];   // 16 KB

    const int wid   = threadIdx.x >> 5;        // local b-row
    const int lane  = threadIdx.x & 31;
    const int ihalf = lane >> 4;               // 0 or 1 : which 512-chunk of i
    const int opair = lane & 15;
    const int b     = blockIdx.y * TBROWS + wid;
    const int o0    = blockIdx.x * 32 + opair * 2;

    // Stage x tile (4 x 1024 floats), coalesced float4.
    {
        const float4* src = (const float4*)(x + (size_t)blockIdx.y * TBROWS * DIN);
        float4*       dst = (float4*)&xs[0][0];
        #pragma unroll
        for (int t = threadIdx.x; t < TBROWS * DIN / 4; t += NTHREADS)
            dst[t] = src[t];
    }
    __syncthreads();

    const float* xrow = &xs[wid][ihalf * 512];
    const float* wbase = w + (size_t)ihalf * 512 * DOUT + o0;

    const ull ABSM = 0x7FFFFFFF7FFFFFFFULL;
    const ull EPS2 = pack2(EPSILON, EPSILON);

    // ---- pass 0: z = x @ W (as c = z/DIN), packed ----
    ull s = 0ULL;
    #pragma unroll 8
    for (int i = 0; i < 512; i++) {
        float xi = xrow[i];
        ull wv = __ldg((const ull*)(wbase + (size_t)i * DOUT));
        s = fma2(pack2(xi, xi), wv, s);
    }
    float s0, s1;
    unpack2(s, s0, s1);
    s0 += __shfl_xor_sync(0xffffffffu, s0, 16);
    s1 += __shfl_xor_sync(0xffffffffu, s1, 16);
    float c0 = s0 * (1.0f / DIN);
    float c1 = s1 * (1.0f / DIN);

    // ---- K IRLS iterations ----
    #pragma unroll 1
    for (int k = 0; k < KITER; k++) {
        ull nc = pack2(-c0, -c1);
        ull sw = 0ULL, swx = 0ULL;
        #pragma unroll 8
        for (int i = 0; i < 512; i++) {
            float xi = xrow[i];
            ull wv = __ldg((const ull*)(wbase + (size_t)i * DOUT));
            ull xw = mul2(pack2(xi, xi), wv);
            ull d  = add2(xw, nc);          // xw - c
            d &= ABSM;                      // |.| on alu pipe (2x LOP3)
            d = add2(d, EPS2);
            float d0, d1;  unpack2(d, d0, d1);
            ull r = pack2(rcpf(d0), rcpf(d1));   // 2x MUFU.RCP
            sw  = add2(sw, r);
            swx = fma2(r, xw, swx);
        }
        float a0, a1, m0, m1;
        unpack2(sw,  a0, a1);
        unpack2(swx, m0, m1);
        a0 += __shfl_xor_sync(0xffffffffu, a0, 16);
        a1 += __shfl_xor_sync(0xffffffffu, a1, 16);
        m0 += __shfl_xor_sync(0xffffffffu, m0, 16);
        m1 += __shfl_xor_sync(0xffffffffu, m1, 16);
        c0 = __fdividef(m0, fmaxf(a0, 1e-12f));
        c1 = __fdividef(m1, fmaxf(a1, 1e-12f));
    }

    if (ihalf == 0) {
        float2 res = make_float2((float)DIN * c0, (float)DIN * c1);
        *(float2*)(out + (size_t)b * DOUT + o0) = res;
    }
}

extern "C" void kernel_launch(void* const* d_in, const int* in_sizes, int n_in,
                              void* d_out, int out_size)
{
    const float* x = (const float*)d_in[0];   // (128, 1024)
    const float* w = (const float*)d_in[1];   // (1024, 1024)
    float* out = (float*)d_out;               // (128, 1024)

    dim3 grid(DOUT / 32, 128 / TBROWS);       // (32, 32) = 1024 blocks
    robust_sum_kernel<<<grid, NTHREADS>>>(x, w, out);
}